// round 13
// baseline (speedup 1.0000x reference)
#include <cuda_runtime.h>
#include <cuda_fp16.h>
#include <cstdint>
#include <math.h>
#include <mma.h>

using namespace nvcuda;

// ---------------------------------------------------------------------------
// PointFeatureAlignment: W[b,cell,g] (3-NN weights / 64) then
// Out[b,d,cell] = sum_g W[b,cell,g] * F[b,g,d]  (wmma fp16 GEMM, split-K=2)
// nn: z-slab pruned EXACT 3-NN. Centers and points binned into 8 z-slabs;
// each point scans slabs outward from its home slab and stops when the
// z-distance lower bound proves no unscanned center can strictly beat the
// 3rd-best. Insertion = exact branchless selects (R8 semantics).
// ---------------------------------------------------------------------------

#define IMAGE_SIZE 224
#define SLABS 8
#define MAX_B 4
#define MAX_G 512
#define MAX_N 25088
#define MAX_W_ELEMS  (MAX_B * 784 * MAX_G)
#define MAX_F_ELEMS  (MAX_B * MAX_G * 384)
#define MAX_O_ELEMS  (MAX_B * 384 * 784)

__device__ float  g_W[MAX_W_ELEMS];
__device__ __half g_Wh[MAX_W_ELEMS];
__device__ __half g_Fh[MAX_F_ELEMS];
__device__ float  g_P[MAX_O_ELEMS];

// slab-sort scratch
__device__ float4 g_cs[MAX_B * MAX_G];        // sorted centers (x,y,z,|s|^2)
__device__ int    g_cidx[MAX_B * MAX_G];      // original center index
__device__ int    g_cstart[MAX_B * (SLABS + 1)];
__device__ float4 g_pts[MAX_B * MAX_N];       // sorted points (x,y,z, cell)
__device__ int    g_pcnt[MAX_B * SLABS];
__device__ int    g_pstart[MAX_B * SLABS + 1];
__device__ int    g_pfill[MAX_B * SLABS];

__device__ __forceinline__ void cp_async16(uint32_t dst, const void* src, int src_bytes) {
    asm volatile("cp.async.cg.shared.global [%0], [%1], 16, %2;"
                 :: "r"(dst), "l"(src), "r"(src_bytes) : "memory");
}
__device__ __forceinline__ void cp_commit() {
    asm volatile("cp.async.commit_group;" ::: "memory");
}
__device__ __forceinline__ uint32_t smem_u32(const void* p) {
    uint32_t a;
    asm("{ .reg .u64 t; cvta.to.shared.u64 t, %1; cvt.u32.u64 %0, t; }"
        : "=r"(a) : "l"(p));
    return a;
}
__device__ __forceinline__ int slab_of(float z) {
    int s = (int)(z * (float)SLABS);
    return min(SLABS - 1, max(0, s));
}

// ---------------------------------------------------------------------------
// Kernel 0: zero W + pcnt scratch, convert F -> fp16
// ---------------------------------------------------------------------------
__global__ void zero_conv_kernel(const float* __restrict__ F, int nW, int nF, int nPC) {
    int i = blockIdx.x * blockDim.x + threadIdx.x;
    int stride = gridDim.x * blockDim.x;
    int nW4 = nW >> 2;
    float4* w4 = reinterpret_cast<float4*>(g_W);
    for (int j = i; j < nW4; j += stride) w4[j] = make_float4(0.f, 0.f, 0.f, 0.f);
    for (int j = i; j < nPC; j += stride) g_pcnt[j] = 0;

    int nF4 = nF >> 2;
    const float4* f4 = reinterpret_cast<const float4*>(F);
    uint2* o4 = reinterpret_cast<uint2*>(g_Fh);
    for (int j = i; j < nF4; j += stride) {
        float4 v = f4[j];
        __half2 h01 = __floats2half2_rn(v.x, v.y);
        __half2 h23 = __floats2half2_rn(v.z, v.w);
        uint2 o;
        o.x = *reinterpret_cast<uint32_t*>(&h01);
        o.y = *reinterpret_cast<uint32_t*>(&h23);
        o4[j] = o;
    }
}

// ---------------------------------------------------------------------------
// Kernel A: bin centers into z-slabs (one block per batch)
// ---------------------------------------------------------------------------
__global__ void bin_centers_kernel(const float* __restrict__ centers, int G) {
    const int b = blockIdx.x;
    __shared__ int cnt[SLABS];
    __shared__ int start[SLABS + 1];
    if (threadIdx.x < SLABS) cnt[threadIdx.x] = 0;
    __syncthreads();

    int myslab[4], mypos[4];
    int it = 0;
    for (int g = threadIdx.x; g < G; g += blockDim.x) {
        float z = centers[((size_t)b * G + g) * 3 + 2];
        int s = slab_of(z);
        myslab[it] = s;
        mypos[it] = atomicAdd(&cnt[s], 1);
        it++;
    }
    __syncthreads();
    if (threadIdx.x == 0) {
        int acc = 0;
        for (int s = 0; s < SLABS; s++) { start[s] = acc; acc += cnt[s]; }
        start[SLABS] = acc;
        for (int s = 0; s <= SLABS; s++) g_cstart[b * (SLABS + 1) + s] = start[s];
    }
    __syncthreads();
    it = 0;
    for (int g = threadIdx.x; g < G; g += blockDim.x) {
        const float* c = centers + ((size_t)b * G + g) * 3;
        float x = c[0], y = c[1], z = c[2];
        int p = start[myslab[it]] + mypos[it];
        it++;
        g_cs[b * MAX_G + p] = make_float4(x, y, z, x * x + y * y + z * z);
        g_cidx[b * MAX_G + p] = g;
    }
}

// ---------------------------------------------------------------------------
// Kernel B1: count points per (batch, slab)
// ---------------------------------------------------------------------------
__global__ void pcount_kernel(const float* __restrict__ points, int B, int N) {
    __shared__ int h[MAX_B * SLABS];
    const int nb = B * SLABS;
    for (int j = threadIdx.x; j < nb; j += blockDim.x) h[j] = 0;
    __syncthreads();
    const int total = B * N;
    for (int i = blockIdx.x * blockDim.x + threadIdx.x; i < total;
         i += gridDim.x * blockDim.x) {
        int b = i / N;
        float z = points[(size_t)i * 3 + 2];
        atomicAdd(&h[b * SLABS + slab_of(z)], 1);
    }
    __syncthreads();
    for (int j = threadIdx.x; j < nb; j += blockDim.x)
        if (h[j]) atomicAdd(&g_pcnt[j], h[j]);
}

// ---------------------------------------------------------------------------
// Kernel B2: scan counts; zero fill counters (single tiny block)
// ---------------------------------------------------------------------------
__global__ void pscan_kernel(int B) {
    if (threadIdx.x == 0) {
        int nb = B * SLABS;
        int acc = 0;
        for (int j = 0; j < nb; j++) { g_pstart[j] = acc; acc += g_pcnt[j]; }
        g_pstart[nb] = acc;
    }
    int nb = B * SLABS;
    for (int j = threadIdx.x; j < nb; j += blockDim.x) g_pfill[j] = 0;
}

// ---------------------------------------------------------------------------
// Kernel B3: scatter points into slab-sorted order (block-aggregated atomics)
// ---------------------------------------------------------------------------
__global__ void pscatter_kernel(const float* __restrict__ points,
                                const int* __restrict__ nzidx,
                                int B, int N, int Ho, int ks) {
    __shared__ int h[MAX_B * SLABS];
    __shared__ int base[MAX_B * SLABS];
    const int nb = B * SLABS;
    const int total = B * N;
    for (int tile = blockIdx.x; tile * blockDim.x < total; tile += gridDim.x) {
        int i = tile * blockDim.x + threadIdx.x;
        for (int j = threadIdx.x; j < nb; j += blockDim.x) h[j] = 0;
        __syncthreads();
        int bin = -1, lpos = 0, cell = 0;
        float x = 0.f, y = 0.f, z = 0.f;
        if (i < total) {
            int b = i / N;
            int n = i - b * N;
            const float* p = points + (size_t)i * 3;
            x = p[0]; y = p[1]; z = p[2];
            bin = b * SLABS + slab_of(z);
            lpos = atomicAdd(&h[bin], 1);
            int idx = nzidx[n];
            int row = idx / IMAGE_SIZE;
            int col = idx - row * IMAGE_SIZE;
            cell = (row / ks) * Ho + (col / ks);
        }
        __syncthreads();
        for (int j = threadIdx.x; j < nb; j += blockDim.x)
            base[j] = h[j] ? atomicAdd(&g_pfill[j], h[j]) : 0;
        __syncthreads();
        if (i < total) {
            int slot = g_pstart[bin] + base[bin] + lpos;
            g_pts[slot] = make_float4(x, y, z, __int_as_float(cell));
        }
        __syncthreads();
    }
}

// ---------------------------------------------------------------------------
// Kernel 1: slab-pruned exact 3-NN over sorted points
// grid: (ceil(N/256), B), block 256.  Batch b's sorted points live at
// g_pts[b*N .. b*N+N) (bins are batch-major, per-batch totals = N).
// ---------------------------------------------------------------------------
__global__ void nn_kernel(int G, int N, int Ho, int ks) {
    __shared__ float4 scs[MAX_G];
    __shared__ int    scidx[MAX_G];
    __shared__ int    sstart[SLABS + 1];
    const int b = blockIdx.y;
    const int tid = threadIdx.x;

    for (int j = tid; j < G; j += blockDim.x) {
        scs[j] = g_cs[b * MAX_G + j];
        scidx[j] = g_cidx[b * MAX_G + j];
    }
    if (tid <= SLABS) sstart[tid] = g_cstart[b * (SLABS + 1) + tid];
    __syncthreads();

    int slot = blockIdx.x * blockDim.x + tid;
    if (slot >= N) return;

    float4 pt = g_pts[(size_t)b * N + slot];
    float tx = pt.x, ty = pt.y, tz = pt.z;
    int cell = __float_as_int(pt.w);
    float ax = -2.0f * tx, ay = -2.0f * ty, az = -2.0f * tz;
    float tt = tx * tx + ty * ty + tz * tz;

    float e0 = 3.4e38f, e1 = 3.4e38f, e2 = 3.4e38f;
    int   i0 = 0, i1 = 0, i2 = 0;

    auto scan_slab = [&](int s) {
        int jb = sstart[s], je = sstart[s + 1];
        for (int j = jb; j < je; j++) {
            float4 c = scs[j];
            float d = fmaf(ax, c.x, fmaf(ay, c.y, fmaf(az, c.z, c.w)));
            bool p0 = d < e0, p1 = d < e1, p2 = d < e2;
            e2 = p1 ? e1 : (p2 ? d : e2);  i2 = p1 ? i1 : (p2 ? j : i2);
            e1 = p0 ? e0 : (p1 ? d : e1);  i1 = p0 ? i0 : (p1 ? j : i1);
            e0 = p0 ? d : e0;              i0 = p0 ? j : i0;
        }
    };

    const float inv_slab = 1.0f / (float)SLABS;
    int s0 = slab_of(tz);
    scan_slab(s0);
    int up = s0 + 1, dn = s0 - 1;
    while (true) {
        float zd_up = (up < SLABS) ? ((float)up * inv_slab - tz) : 3.4e38f;
        float zd_dn = (dn >= 0)    ? (tz - (float)(dn + 1) * inv_slab) : 3.4e38f;
        float zd = fminf(zd_up, zd_dn);
        // lower bound on d^2 of any center in the nearest unscanned slab;
        // stop when it cannot STRICTLY beat the 3rd best (d^2 = e2 + tt).
        if (zd * zd >= e2 + tt) break;
        if (zd_up <= zd_dn) { scan_slab(up); up++; }
        else                { scan_slab(dn); dn--; }
    }

    float d0 = fmaxf(e0 + tt, 1e-10f);
    float d1 = fmaxf(e1 + tt, 1e-10f);
    float d2 = fmaxf(e2 + tt, 1e-10f);
    float r0 = 1.0f / d0, r1 = 1.0f / d1, r2 = 1.0f / d2;
    float inv = 1.0f / ((r0 + r1 + r2) * (float)(ks * ks));

    float* Wrow = g_W + ((size_t)b * Ho * Ho + cell) * G;
    atomicAdd(Wrow + scidx[i0], r0 * inv);
    atomicAdd(Wrow + scidx[i1], r1 * inv);
    atomicAdd(Wrow + scidx[i2], r2 * inv);
}

// ---------------------------------------------------------------------------
// Kernel 1b: convert accumulated W (fp32) -> fp16
// ---------------------------------------------------------------------------
__global__ void convw_kernel(int nW) {
    int i = blockIdx.x * blockDim.x + threadIdx.x;
    int stride = gridDim.x * blockDim.x;
    int nW4 = nW >> 2;
    const float4* w4 = reinterpret_cast<const float4*>(g_W);
    uint2* o4 = reinterpret_cast<uint2*>(g_Wh);
    for (int j = i; j < nW4; j += stride) {
        float4 v = w4[j];
        __half2 h01 = __floats2half2_rn(v.x, v.y);
        __half2 h23 = __floats2half2_rn(v.z, v.w);
        uint2 o;
        o.x = *reinterpret_cast<uint32_t*>(&h01);
        o.y = *reinterpret_cast<uint32_t*>(&h23);
        o4[j] = o;
    }
}

// ---------------------------------------------------------------------------
// Kernel 2: wmma fp16 GEMM (fp32 accum), split-K = 2  (frozen; 15.1us)
// ---------------------------------------------------------------------------
#define KC 32
#define A_LDM 136
#define B_LDM 40
#define A_SZ (KC * A_LDM)
#define B_SZ (64 * B_LDM)
#define ST_LDM 72

struct __align__(32) GSmem {
    union {
        struct { __half As[2][A_SZ]; __half Bs[2][B_SZ]; } b;
        float stage[128 * ST_LDM];
    };
};

__global__ void __launch_bounds__(256) gemm_wmma_kernel(
        float* __restrict__ out, int G, int Dim, int HoHo) {
    __shared__ GSmem sm;

    const int tid = threadIdx.x;
    const int wid = tid >> 5;
    const int wy = wid >> 1;
    const int wx = wid & 1;
    const int bz = blockIdx.z;
    const int b     = bz >> 1;
    const int slice = bz & 1;
    const int d0 = blockIdx.y * 128;
    const int c0 = blockIdx.x * 64;

    const int Kh    = G >> 1;
    const int kbase = slice * Kh;

    const __half* Fb = g_Fh + (size_t)b * G * Dim;
    const __half* Wb = g_Wh + (size_t)b * HoHo * G;
    float* dst = slice ? g_P : out;

    const uint32_t smA = smem_u32(sm.b.As[0]);
    const uint32_t smB = smem_u32(sm.b.Bs[0]);

    wmma::fragment<wmma::accumulator, 16, 16, 16, float> acc[2][2];
#pragma unroll
    for (int i = 0; i < 2; i++)
#pragma unroll
        for (int j = 0; j < 2; j++) wmma::fill_fragment(acc[i][j], 0.0f);

    auto load_chunk = [&](int c, int buf) {
        const int g0 = kbase + c * KC;
#pragma unroll
        for (int r = 0; r < 2; r++) {
            int op = r * 256 + tid;
            int k  = op >> 4;
            int d8 = op & 15;
            const __half* src = Fb + (size_t)(g0 + k) * Dim + d0 + d8 * 8;
            int bytes = (d0 + d8 * 8 + 8 <= Dim) ? 16 : 0;
            cp_async16(smA + (uint32_t)(buf * A_SZ + k * A_LDM + d8 * 8) * 2, src, bytes);
        }
        {
            int n  = tid >> 2;
            int kq = tid & 3;
            const __half* src = Wb + (size_t)(c0 + n) * G + g0 + kq * 8;
            int bytes = (c0 + n < HoHo) ? 16 : 0;
            cp_async16(smB + (uint32_t)(buf * B_SZ + n * B_LDM + kq * 8) * 2, src, bytes);
        }
        cp_commit();
    };

    const int NC = Kh / KC;
    load_chunk(0, 0);

    for (int c = 0; c < NC; c++) {
        const int buf = c & 1;
        if (c + 1 < NC) {
            load_chunk(c + 1, (c + 1) & 1);
            asm volatile("cp.async.wait_group 1;" ::: "memory");
        } else {
            asm volatile("cp.async.wait_group 0;" ::: "memory");
        }
        __syncthreads();

        const __half* As = sm.b.As[buf];
        const __half* Bs = sm.b.Bs[buf];
#pragma unroll
        for (int ks = 0; ks < KC; ks += 16) {
            wmma::fragment<wmma::matrix_a, 16, 16, 16, __half, wmma::col_major> af[2];
            wmma::fragment<wmma::matrix_b, 16, 16, 16, __half, wmma::col_major> bf[2];
#pragma unroll
            for (int fi = 0; fi < 2; fi++)
                wmma::load_matrix_sync(af[fi], As + ks * A_LDM + wy * 32 + fi * 16, A_LDM);
#pragma unroll
            for (int fj = 0; fj < 2; fj++)
                wmma::load_matrix_sync(bf[fj], Bs + (wx * 32 + fj * 16) * B_LDM + ks, B_LDM);
#pragma unroll
            for (int fi = 0; fi < 2; fi++)
#pragma unroll
                for (int fj = 0; fj < 2; fj++)
                    wmma::mma_sync(acc[fi][fj], af[fi], bf[fj], acc[fi][fj]);
        }
        __syncthreads();
    }

#pragma unroll
    for (int fi = 0; fi < 2; fi++)
#pragma unroll
        for (int fj = 0; fj < 2; fj++)
            wmma::store_matrix_sync(
                sm.stage + (wy * 32 + fi * 16) * ST_LDM + wx * 32 + fj * 16,
                acc[fi][fj], ST_LDM, wmma::mem_row_major);
    __syncthreads();

    {
        const int row = tid >> 1;
        const int cb  = (tid & 1) * 32;
        const int d = d0 + row;
        if (d < Dim) {
            float* orow = dst + ((size_t)b * Dim + d) * HoHo;
            const float* srow = sm.stage + row * ST_LDM + cb;
#pragma unroll
            for (int j = 0; j < 32; j += 4) {
                int cc = c0 + cb + j;
                if (cc + 4 <= HoHo) {
                    float4 v = *reinterpret_cast<const float4*>(srow + j);
                    *reinterpret_cast<float4*>(orow + cc) = v;
                } else {
#pragma unroll
                    for (int q = 0; q < 4; q++)
                        if (cc + q < HoHo) orow[cc + q] = srow[j + q];
                }
            }
        }
    }
}

// ---------------------------------------------------------------------------
// Kernel 3: merge split-K partial sums
// ---------------------------------------------------------------------------
__global__ void add_kernel(float* __restrict__ out, int nOut) {
    int i = blockIdx.x * blockDim.x + threadIdx.x;
    int stride = gridDim.x * blockDim.x;
    int n4 = nOut >> 2;
    float4* o4 = reinterpret_cast<float4*>(out);
    const float4* p4 = reinterpret_cast<const float4*>(g_P);
    for (int j = i; j < n4; j += stride) {
        float4 a = o4[j];
        float4 p = p4[j];
        a.x += p.x; a.y += p.y; a.z += p.z; a.w += p.w;
        o4[j] = a;
    }
}

// ---------------------------------------------------------------------------
// Launch
// ---------------------------------------------------------------------------
extern "C" void kernel_launch(void* const* d_in, const int* in_sizes, int n_in,
                              void* d_out, int out_size) {
    const float* group_features = (const float*)d_in[0];  // (B, G, Dim)
    const float* group_centers  = (const float*)d_in[1];  // (B, G, 3)
    const float* original_pts   = (const float*)d_in[2];  // (B, N, 3)
    const int*   nonzero_idx    = (const int*)d_in[3];    // (N)

    const int N   = in_sizes[3];
    const int B   = in_sizes[2] / (3 * N);
    const int Dim = (int)(3LL * in_sizes[0] / in_sizes[1]);
    const int G   = in_sizes[1] / (3 * B);
    const int HoHo = out_size / (B * Dim);
    int Ho = 1;
    while ((Ho + 1) * (Ho + 1) <= HoHo) Ho++;     // integer sqrt
    const int ks = IMAGE_SIZE / Ho;

    const int nW = B * HoHo * G;
    const int nF = B * G * Dim;

    zero_conv_kernel<<<512, 256>>>(group_features, nW, nF, B * SLABS);

    bin_centers_kernel<<<B, 256>>>(group_centers, G);
    pcount_kernel<<<296, 256>>>(original_pts, B, N);
    pscan_kernel<<<1, 64>>>(B);
    pscatter_kernel<<<392, 256>>>(original_pts, nonzero_idx, B, N, Ho, ks);

    dim3 nnGrid((N + 255) / 256, B);
    nn_kernel<<<nnGrid, 256>>>(G, N, Ho, ks);

    convw_kernel<<<512, 256>>>(nW);

    dim3 gGrid((HoHo + 63) / 64, (Dim + 127) / 128, B * 2);
    gemm_wmma_kernel<<<gGrid, 256>>>((float*)d_out, G, Dim, HoHo);

    add_kernel<<<296, 256>>>((float*)d_out, out_size);
}

// round 14
// speedup vs baseline: 1.1268x; 1.1268x over previous
#include <cuda_runtime.h>
#include <cuda_fp16.h>
#include <cstdint>
#include <math.h>
#include <mma.h>

using namespace nvcuda;

// ---------------------------------------------------------------------------
// PointFeatureAlignment: W[b,cell,g] (3-NN weights / 64) then
// Out[b,d,cell] = sum_g W[b,cell,g] * F[b,g,d]
// nn: R12 exact branchless top-3 with warp-vote skip (FROZEN — any change
//     that can alter selection is banned: R6/R10/R13 evidence).
// GEMM: wmma fp16 m16n16k16, fp32 accum, split-K=2, 3-stage cp.async ring;
//       both slices RED.F32 into a zeroed out (no merge kernel; fp32 add is
//       commutative so the result is replay-deterministic).
// ---------------------------------------------------------------------------

#define IMAGE_SIZE 224
#define MAX_W_ELEMS  (4 * 784 * 512)
#define MAX_F_ELEMS  (4 * 512 * 384)

__device__ float  g_W[MAX_W_ELEMS];      // fp32 atomic accumulation target
__device__ __half g_Wh[MAX_W_ELEMS];     // fp16 copy for GEMM
__device__ __half g_Fh[MAX_F_ELEMS];     // fp16 features

__device__ __forceinline__ void cp_async16(uint32_t dst, const void* src, int src_bytes) {
    asm volatile("cp.async.cg.shared.global [%0], [%1], 16, %2;"
                 :: "r"(dst), "l"(src), "r"(src_bytes) : "memory");
}
__device__ __forceinline__ void cp_commit() {
    asm volatile("cp.async.commit_group;" ::: "memory");
}
__device__ __forceinline__ uint32_t smem_u32(const void* p) {
    uint32_t a;
    asm("{ .reg .u64 t; cvta.to.shared.u64 t, %1; cvt.u32.u64 %0, t; }"
        : "=r"(a) : "l"(p));
    return a;
}

// ---------------------------------------------------------------------------
// Kernel 0: zero W scratch + zero out + convert F -> fp16
// ---------------------------------------------------------------------------
__global__ void zero_conv_kernel(const float* __restrict__ F,
                                 float* __restrict__ out,
                                 int nW, int nF, int nOut) {
    int i = blockIdx.x * blockDim.x + threadIdx.x;
    int stride = gridDim.x * blockDim.x;
    int nW4 = nW >> 2;
    float4* w4 = reinterpret_cast<float4*>(g_W);
    for (int j = i; j < nW4; j += stride) w4[j] = make_float4(0.f, 0.f, 0.f, 0.f);

    int nO4 = nOut >> 2;
    float4* o4f = reinterpret_cast<float4*>(out);
    for (int j = i; j < nO4; j += stride) o4f[j] = make_float4(0.f, 0.f, 0.f, 0.f);

    int nF4 = nF >> 2;
    const float4* f4 = reinterpret_cast<const float4*>(F);
    uint2* o4 = reinterpret_cast<uint2*>(g_Fh);
    for (int j = i; j < nF4; j += stride) {
        float4 v = f4[j];
        __half2 h01 = __floats2half2_rn(v.x, v.y);
        __half2 h23 = __floats2half2_rn(v.z, v.w);
        uint2 o;
        o.x = *reinterpret_cast<uint32_t*>(&h01);
        o.y = *reinterpret_cast<uint32_t*>(&h23);
        o4[j] = o;
    }
}

// ---------------------------------------------------------------------------
// Kernel 1: per-point 3-NN; exact branchless top-3 with warp-vote skip.
// (FROZEN R12 version)
// ---------------------------------------------------------------------------
__global__ void nn_kernel(const float* __restrict__ centers,  // (B, G, 3)
                          const float* __restrict__ points,   // (B, N, 3)
                          const int*   __restrict__ nzidx,    // (N)
                          int G, int N, int Ho, int ks) {
    extern __shared__ float4 sc[];   // G entries: (x, y, z, |s|^2)
    const int b = blockIdx.y;

    const float* cb = centers + (size_t)b * G * 3;
    for (int g = threadIdx.x; g < G; g += blockDim.x) {
        float x = cb[g * 3 + 0];
        float y = cb[g * 3 + 1];
        float z = cb[g * 3 + 2];
        sc[g] = make_float4(x, y, z, x * x + y * y + z * z);
    }
    __syncthreads();

    int nr = blockIdx.x * blockDim.x + threadIdx.x;
    bool valid = nr < N;
    int n = valid ? nr : 0;

    const float* p = points + ((size_t)b * N + n) * 3;
    float tx = p[0], ty = p[1], tz = p[2];
    float ax = -2.0f * tx, ay = -2.0f * ty, az = -2.0f * tz;
    float tt = tx * tx + ty * ty + tz * tz;

    float e0 = 3.4e38f, e1 = 3.4e38f, e2 = 3.4e38f;
    int   i0 = 0, i1 = 0, i2 = 0;

#pragma unroll 4
    for (int g = 0; g < G; g++) {
        float4 c = sc[g];
        float d = fmaf(ax, c.x, fmaf(ay, c.y, fmaf(az, c.z, c.w)));
        bool p2 = d < e2;
        if (__any_sync(0xFFFFFFFFu, p2)) {      // warp-uniform skip
            bool p0 = d < e0;
            bool p1 = d < e1;
            e2 = p1 ? e1 : (p2 ? d : e2);
            i2 = p1 ? i1 : (p2 ? g : i2);
            e1 = p0 ? e0 : (p1 ? d : e1);
            i1 = p0 ? i0 : (p1 ? g : i1);
            e0 = p0 ? d : e0;
            i0 = p0 ? g : i0;
        }
    }

    if (valid) {
        float d0 = fmaxf(e0 + tt, 1e-10f);
        float d1 = fmaxf(e1 + tt, 1e-10f);
        float d2 = fmaxf(e2 + tt, 1e-10f);
        float r0 = 1.0f / d0, r1 = 1.0f / d1, r2 = 1.0f / d2;
        float inv = 1.0f / ((r0 + r1 + r2) * (float)(ks * ks));

        int idx = nzidx[n];
        int row = idx / IMAGE_SIZE;
        int col = idx - row * IMAGE_SIZE;
        int cell = (row / ks) * Ho + (col / ks);

        float* Wrow = g_W + ((size_t)b * Ho * Ho + cell) * G;
        atomicAdd(Wrow + i0, r0 * inv);
        atomicAdd(Wrow + i1, r1 * inv);
        atomicAdd(Wrow + i2, r2 * inv);
    }
}

// ---------------------------------------------------------------------------
// Kernel 1b: convert accumulated W (fp32) -> fp16
// ---------------------------------------------------------------------------
__global__ void convw_kernel(int nW) {
    int i = blockIdx.x * blockDim.x + threadIdx.x;
    int stride = gridDim.x * blockDim.x;
    int nW4 = nW >> 2;
    const float4* w4 = reinterpret_cast<const float4*>(g_W);
    uint2* o4 = reinterpret_cast<uint2*>(g_Wh);
    for (int j = i; j < nW4; j += stride) {
        float4 v = w4[j];
        __half2 h01 = __floats2half2_rn(v.x, v.y);
        __half2 h23 = __floats2half2_rn(v.z, v.w);
        uint2 o;
        o.x = *reinterpret_cast<uint32_t*>(&h01);
        o.y = *reinterpret_cast<uint32_t*>(&h23);
        o4[j] = o;
    }
}

// ---------------------------------------------------------------------------
// Kernel 2: wmma fp16 GEMM (fp32 accum), split-K = 2, 3-stage cp.async ring.
// Both slices RED.F32 into the zeroed out buffer (no merge kernel).
// CTA: 128(d) x 64(c), 8 warps (4x2), warp tile 32x32 (2x2 m16n16k16).
// grid: (HoHo/64, Dim/128, B*2)
// ---------------------------------------------------------------------------
#define KC 32
#define A_LDM 136
#define B_LDM 40
#define A_SZ (KC * A_LDM)     // 4352 halves
#define B_SZ (64 * B_LDM)     // 2560 halves
#define ST_LDM 72
#define STAGES 3

struct __align__(32) GSmem {
    union {
        struct { __half As[STAGES][A_SZ]; __half Bs[STAGES][B_SZ]; } b;  // 41.5 KB
        float stage[128 * ST_LDM];                                       // 36.9 KB
    };
};

__global__ void __launch_bounds__(256) gemm_wmma_kernel(
        float* __restrict__ out,       // (B, Dim, HoHo)
        int G, int Dim, int HoHo) {
    __shared__ GSmem sm;

    const int tid = threadIdx.x;
    const int wid = tid >> 5;
    const int wy = wid >> 1;
    const int wx = wid & 1;
    const int bz = blockIdx.z;
    const int b     = bz >> 1;
    const int slice = bz & 1;
    const int d0 = blockIdx.y * 128;
    const int c0 = blockIdx.x * 64;

    const int Kh    = G >> 1;
    const int kbase = slice * Kh;

    const __half* Fb = g_Fh + (size_t)b * G * Dim;
    const __half* Wb = g_Wh + (size_t)b * HoHo * G;

    const uint32_t smA = smem_u32(sm.b.As[0]);
    const uint32_t smB = smem_u32(sm.b.Bs[0]);

    wmma::fragment<wmma::accumulator, 16, 16, 16, float> acc[2][2];
#pragma unroll
    for (int i = 0; i < 2; i++)
#pragma unroll
        for (int j = 0; j < 2; j++) wmma::fill_fragment(acc[i][j], 0.0f);

    auto load_chunk = [&](int c, int buf) {
        const int g0 = kbase + c * KC;
#pragma unroll
        for (int r = 0; r < 2; r++) {
            int op = r * 256 + tid;
            int k  = op >> 4;
            int d8 = op & 15;
            const __half* src = Fb + (size_t)(g0 + k) * Dim + d0 + d8 * 8;
            int bytes = (d0 + d8 * 8 + 8 <= Dim) ? 16 : 0;
            cp_async16(smA + (uint32_t)(buf * A_SZ + k * A_LDM + d8 * 8) * 2, src, bytes);
        }
        {
            int n  = tid >> 2;
            int kq = tid & 3;
            const __half* src = Wb + (size_t)(c0 + n) * G + g0 + kq * 8;
            int bytes = (c0 + n < HoHo) ? 16 : 0;
            cp_async16(smB + (uint32_t)(buf * B_SZ + n * B_LDM + kq * 8) * 2, src, bytes);
        }
        cp_commit();
    };

    const int NC = Kh / KC;           // 8 here
    load_chunk(0, 0);
    if (NC > 1) load_chunk(1, 1);

    for (int c = 0; c < NC; c++) {
        const int buf = c % STAGES;
        if (c + 2 < NC) {
            load_chunk(c + 2, (c + 2) % STAGES);
            asm volatile("cp.async.wait_group 2;" ::: "memory");
        } else if (c + 1 < NC) {
            asm volatile("cp.async.wait_group 1;" ::: "memory");
        } else {
            asm volatile("cp.async.wait_group 0;" ::: "memory");
        }
        __syncthreads();

        const __half* As = sm.b.As[buf];
        const __half* Bs = sm.b.Bs[buf];
#pragma unroll
        for (int ks = 0; ks < KC; ks += 16) {
            wmma::fragment<wmma::matrix_a, 16, 16, 16, __half, wmma::col_major> af[2];
            wmma::fragment<wmma::matrix_b, 16, 16, 16, __half, wmma::col_major> bf[2];
#pragma unroll
            for (int fi = 0; fi < 2; fi++)
                wmma::load_matrix_sync(af[fi], As + ks * A_LDM + wy * 32 + fi * 16, A_LDM);
#pragma unroll
            for (int fj = 0; fj < 2; fj++)
                wmma::load_matrix_sync(bf[fj], Bs + (wx * 32 + fj * 16) * B_LDM + ks, B_LDM);
#pragma unroll
            for (int fi = 0; fi < 2; fi++)
#pragma unroll
                for (int fj = 0; fj < 2; fj++)
                    wmma::mma_sync(acc[fi][fj], af[fi], bf[fj], acc[fi][fj]);
        }
        __syncthreads();
    }

    // --- epilogue: frags -> smem stage -> coalesced RED.F32 into out ---
#pragma unroll
    for (int fi = 0; fi < 2; fi++)
#pragma unroll
        for (int fj = 0; fj < 2; fj++)
            wmma::store_matrix_sync(
                sm.stage + (wy * 32 + fi * 16) * ST_LDM + wx * 32 + fj * 16,
                acc[fi][fj], ST_LDM, wmma::mem_row_major);
    __syncthreads();

    {
        const int row = tid >> 1;
        const int cb  = (tid & 1) * 32;
        const int d = d0 + row;
        if (d < Dim) {
            float* orow = out + ((size_t)b * Dim + d) * HoHo;
            const float* srow = sm.stage + row * ST_LDM + cb;
#pragma unroll
            for (int j = 0; j < 32; j++) {
                int cc = c0 + cb + j;
                if (cc < HoHo) atomicAdd(orow + cc, srow[j]);   // RED.F32 (no return)
            }
        }
    }
}

// ---------------------------------------------------------------------------
// Launch
// ---------------------------------------------------------------------------
extern "C" void kernel_launch(void* const* d_in, const int* in_sizes, int n_in,
                              void* d_out, int out_size) {
    const float* group_features = (const float*)d_in[0];  // (B, G, Dim)
    const float* group_centers  = (const float*)d_in[1];  // (B, G, 3)
    const float* original_pts   = (const float*)d_in[2];  // (B, N, 3)
    const int*   nonzero_idx    = (const int*)d_in[3];    // (N)

    const int N   = in_sizes[3];
    const int B   = in_sizes[2] / (3 * N);
    const int Dim = (int)(3LL * in_sizes[0] / in_sizes[1]);
    const int G   = in_sizes[1] / (3 * B);
    const int HoHo = out_size / (B * Dim);
    int Ho = 1;
    while ((Ho + 1) * (Ho + 1) <= HoHo) Ho++;     // integer sqrt
    const int ks = IMAGE_SIZE / Ho;

    const int nW = B * HoHo * G;
    const int nF = B * G * Dim;

    zero_conv_kernel<<<512, 256>>>(group_features, (float*)d_out, nW, nF, out_size);

    dim3 nnGrid((N + 255) / 256, B);
    size_t smem = (size_t)G * sizeof(float4);
    nn_kernel<<<nnGrid, 256, smem>>>(group_centers, original_pts, nonzero_idx,
                                     G, N, Ho, ks);

    convw_kernel<<<512, 256>>>(nW);

    dim3 gGrid((HoHo + 63) / 64, (Dim + 127) / 128, B * 2);
    gemm_wmma_kernel<<<gGrid, 256>>>((float*)d_out, G, Dim, HoHo);
}